// round 14
// baseline (speedup 1.0000x reference)
#include <cuda_runtime.h>
#include <cstdint>
#include <cstddef>

#define BATCH 16
#define CDIM  512
#define HW    2304
#define NLBLK 144          // 2304/16  (A m-blocks)
#define NNBLK 288          // 2304/8   (B n-blocks)
#define NKS   64           // 512/8    (k-steps)
#define NCH   16           // chunks of 32 c per tile
#define NLT   18           // l-tiles per column strip

// Staged transposed A (tf32 bits), c-contiguous: g_At[b][l][c], l = w*48+h.
__device__ uint32_t g_At[(size_t)BATCH * HW * CDIM];        // 75.5 MB
// Fragment-packed tf32 operands (bit patterns in uint32):
//  g_Apk[b][lblk][kstep][lane] = {a0,a1,a2,a3} for m16n8k8 row-major A,
//      a_j: row = lblk*16 + (lane>>2) + (j&1)*8,  c = kstep*8 + (lane&3) + (j>>1)*4
//  g_Bpk[b][nblk][kstep][lane] = {b0,b1} for col-major B,
//      b_j: c = kstep*8 + (lane&3) + j*4,  n = nblk*8 + (lane>>2)
__device__ uint4 g_Apk[(size_t)BATCH * NLBLK * NKS * 32];   // 75.5 MB
__device__ uint2 g_Bpk[(size_t)BATCH * NNBLK * NKS * 32];   // 75.5 MB

// ---------------------------------------------------------------------------
static __device__ __forceinline__ uint32_t s2u(const void* p) {
    uint32_t a;
    asm("{ .reg .u64 t; cvta.to.shared.u64 t, %1; cvt.u32.u64 %0, t; }"
        : "=r"(a) : "l"(p));
    return a;
}
static __device__ __forceinline__ uint32_t cvt_tf32(float x) {
    uint32_t u;
    asm("cvt.rn.tf32.f32 %0, %1;" : "=r"(u) : "f"(x));
    return u;
}
static __device__ __forceinline__ void cp16(uint32_t dst, const void* src) {
    asm volatile("cp.async.ca.shared.global [%0], [%1], 16;"
                 :: "r"(dst), "l"(src) : "memory");
}

// ---------------------------------------------------------------------------
// Stage 1: 32x32 tiled c-transpose with tf32 round + h/w swap.
//   in : float [b][512 c][2304 m]   (m = h*48+w contiguous)
//   out: tf32  [b][2304 l][512 c]   l = (m%48)*48 + m/48   (= w*48+h)
// Reads coalesced along m; writes coalesced along c.
// ---------------------------------------------------------------------------
__global__ void pack_transpose_kernel(const float* __restrict__ in,
                                      uint32_t* __restrict__ out) {
    __shared__ float t[32][33];
    const int b  = blockIdx.z;
    const int c0 = blockIdx.y * 32;
    const int m0 = blockIdx.x * 32;
    const int tx = threadIdx.x;          // 0..31
    const int ty = threadIdx.y;          // 0..7
    const float* ip = in + (size_t)b * CDIM * HW;
    uint32_t* op = out + (size_t)b * HW * CDIM;
    #pragma unroll
    for (int i = 0; i < 4; i++)
        t[ty + 8 * i][tx] = ip[(size_t)(c0 + ty + 8 * i) * HW + m0 + tx];
    __syncthreads();
    #pragma unroll
    for (int i = 0; i < 4; i++) {
        const int m = m0 + ty + 8 * i;
        const int l = (m % 48) * 48 + m / 48;
        op[(size_t)l * CDIM + c0 + tx] = cvt_tf32(t[tx][ty + 8 * i]);
    }
}

// ---------------------------------------------------------------------------
// Stage 2: fragment-pack A from staged At (all reads full-sector, writes
// contiguous). Output bit-identical to a direct gather pack.
// ---------------------------------------------------------------------------
__global__ void packA2_kernel(const uint32_t* __restrict__ At,
                              uint4* __restrict__ out) {
    const size_t t = (size_t)blockIdx.x * 256 + threadIdx.x;
    const int lane  = (int)(t & 31);
    const int kstep = (int)((t >> 5) & 63);
    const int bl    = (int)(t >> 11);         // b*144 + lblk
    const int b     = bl / NLBLK;
    const int lblk  = bl - b * NLBLK;
    const int gid = lane >> 2, tig = lane & 3;
    const int c0 = kstep * 8 + tig, c1 = c0 + 4;
    const int l0 = lblk * 16 + gid, l1 = l0 + 8;
    const uint32_t* Ab = At + (size_t)b * HW * CDIM;
    uint4 v;
    v.x = Ab[(size_t)l0 * CDIM + c0];
    v.y = Ab[(size_t)l1 * CDIM + c0];
    v.z = Ab[(size_t)l0 * CDIM + c1];
    v.w = Ab[(size_t)l1 * CDIM + c1];
    out[t] = v;
}

// ---------------------------------------------------------------------------
// Pack B: one thread per output uint2 (reads already full-sector).
// ---------------------------------------------------------------------------
__global__ void packB_kernel(const float* __restrict__ in,
                             uint2* __restrict__ out) {
    const size_t t = (size_t)blockIdx.x * 256 + threadIdx.x;
    const int lane  = (int)(t & 31);
    const int kstep = (int)((t >> 5) & 63);
    const int bk    = (int)(t >> 11);         // b*288 + nblk
    const int b     = bk / NNBLK;
    const int nblk  = bk - b * NNBLK;
    const int gid = lane >> 2, tig = lane & 3;
    const int kind = nblk * 8 + gid;
    const int c0 = kstep * 8 + tig;
    const float* ib = in + (size_t)b * CDIM * HW;
    uint2 v;
    v.x = cvt_tf32(ib[(size_t)c0 * HW + kind]);
    v.y = cvt_tf32(ib[(size_t)(c0 + 4) * HW + kind]);
    out[t] = v;
}

// ---------------------------------------------------------------------------
// Column-strip fused GEMM (tf32 mma.sync) + ReLU + L2-normalize.
// Grid (18 k-strips, 16 b), 256 threads = 8 warps (warp_m = wid&1 -> 64 rows,
// warp_n = wid>>1 -> 32 cols). Per 128x128 tile: 16 chunks of 32 c.
// cp.async double buffer: copy of chunk ch+1 overlaps compute of chunk ch.
// colsq accumulated from D registers (no output re-read); in-place rescale.
// ---------------------------------------------------------------------------
__global__ __launch_bounds__(256)
void corr_mma_kernel(const uint4* __restrict__ Apk,
                     const uint2* __restrict__ Bpk,
                     float* __restrict__ out) {
    extern __shared__ unsigned char smd[];
    uint4* As4 = (uint4*)smd;                    // [2][1024] : 32 KB
    uint2* Bs2 = (uint2*)(smd + 32768);          // [2][2048] : 32 KB
    __shared__ float red[128];

    const int tid  = threadIdx.x;
    const int wid  = tid >> 5;
    const int lane = tid & 31;
    const int gid = lane >> 2, tig = lane & 3;
    const int warp_m = wid & 1;
    const int warp_n = wid >> 1;
    const int b   = blockIdx.y;
    const int kb0 = blockIdx.x * 16;             // nblk base of strip
    const int k0  = blockIdx.x * 128;

    const uint4* Ab = Apk + (size_t)b * NLBLK * NKS * 32;
    const uint4* Bb4 = (const uint4*)(Bpk + (size_t)b * NNBLK * NKS * 32);
    float* outb = out + (size_t)b * HW * HW;

    const uint32_t sA = s2u(As4);
    const uint32_t sB = s2u(Bs2);

    if (tid < 128) red[tid] = 0.0f;

    float cs[4][2];
    #pragma unroll
    for (int ni = 0; ni < 4; ni++) { cs[ni][0] = 0.f; cs[ni][1] = 0.f; }

    #pragma unroll 1
    for (int lt = 0; lt < NLT; lt++) {
        float d[4][4][4];
        #pragma unroll
        for (int mi = 0; mi < 4; mi++)
            #pragma unroll
            for (int ni = 0; ni < 4; ni++)
                #pragma unroll
                for (int j = 0; j < 4; j++) d[mi][ni][j] = 0.f;

        // prologue: chunk 0 -> buf 0
        #pragma unroll
        for (int i = 0; i < 4; i++) {
            const int idx = tid + i * 256;                 // 0..1023
            const int blk = idx >> 5, ln = idx & 31;       // A: blk = lb*4+s
            const int lb = blk >> 2, s = blk & 3;
            cp16(sA + (uint32_t)idx * 16u,
                 Ab + ((size_t)((lt * 8 + lb) * 64 + s) * 32 + ln));
            const int blkb = idx >> 4, ln2 = idx & 15;     // B: blkb = nb*4+s
            const int nb = blkb >> 2, s2 = blkb & 3;
            cp16(sB + (uint32_t)idx * 16u,
                 Bb4 + ((size_t)((kb0 + nb) * 64 + s2) * 16 + ln2));
        }
        asm volatile("cp.async.commit_group;" ::: "memory");

        #pragma unroll 1
        for (int ch = 0; ch < NCH; ch++) {
            const int buf = ch & 1;
            asm volatile("cp.async.wait_group 0;" ::: "memory");
            __syncthreads();
            if (ch + 1 < NCH) {
                const int nbuf = buf ^ 1;
                const int kk4 = (ch + 1) * 4;
                #pragma unroll
                for (int i = 0; i < 4; i++) {
                    const int idx = tid + i * 256;
                    const int blk = idx >> 5, ln = idx & 31;
                    const int lb = blk >> 2, s = blk & 3;
                    cp16(sA + (uint32_t)(nbuf * 1024 + idx) * 16u,
                         Ab + ((size_t)((lt * 8 + lb) * 64 + kk4 + s) * 32 + ln));
                    const int blkb = idx >> 4, ln2 = idx & 15;
                    const int nb = blkb >> 2, s2 = blkb & 3;
                    cp16(sB + (uint32_t)(nbuf * 1024 + idx) * 16u,
                         Bb4 + ((size_t)((kb0 + nb) * 64 + kk4 + s2) * 16 + ln2));
                }
                asm volatile("cp.async.commit_group;" ::: "memory");
            }

            // compute: 4 k-steps x (4 m x 4 n) m16n8k8
            #pragma unroll
            for (int s = 0; s < 4; s++) {
                uint4 af[4];
                uint2 bf[4];
                #pragma unroll
                for (int mi = 0; mi < 4; mi++)
                    af[mi] = As4[buf * 1024 + ((warp_m * 4 + mi) * 4 + s) * 32 + lane];
                #pragma unroll
                for (int ni = 0; ni < 4; ni++)
                    bf[ni] = Bs2[buf * 2048 + ((warp_n * 4 + ni) * 4 + s) * 32 + lane];
                #pragma unroll
                for (int mi = 0; mi < 4; mi++) {
                    #pragma unroll
                    for (int ni = 0; ni < 4; ni++) {
                        asm volatile(
                            "mma.sync.aligned.m16n8k8.row.col.f32.tf32.tf32.f32 "
                            "{%0,%1,%2,%3}, {%4,%5,%6,%7}, {%8,%9}, {%0,%1,%2,%3};"
                            : "+f"(d[mi][ni][0]), "+f"(d[mi][ni][1]),
                              "+f"(d[mi][ni][2]), "+f"(d[mi][ni][3])
                            : "r"(af[mi].x), "r"(af[mi].y),
                              "r"(af[mi].z), "r"(af[mi].w),
                              "r"(bf[ni].x), "r"(bf[ni].y));
                    }
                }
            }
        }

        // epilogue: relu, store, colsq from registers
        const int l0 = lt * 128;
        #pragma unroll
        for (int mi = 0; mi < 4; mi++) {
            #pragma unroll
            for (int p = 0; p < 2; p++) {
                const int row = l0 + warp_m * 64 + mi * 16 + gid + p * 8;
                float* rp = outb + (size_t)row * HW + k0 + warp_n * 32 + tig * 2;
                #pragma unroll
                for (int ni = 0; ni < 4; ni++) {
                    float v0 = fmaxf(d[mi][ni][p * 2 + 0], 0.f);
                    float v1 = fmaxf(d[mi][ni][p * 2 + 1], 0.f);
                    cs[ni][0] = fmaf(v0, v0, cs[ni][0]);
                    cs[ni][1] = fmaf(v1, v1, cs[ni][1]);
                    float2 st; st.x = v0; st.y = v1;
                    *(float2*)(rp + ni * 8) = st;
                }
            }
        }
    }

    // strip-end: reduce colsq -> inv norm -> in-place rescale
    __syncthreads();
    #pragma unroll
    for (int ni = 0; ni < 4; ni++) {
        atomicAdd(&red[warp_n * 32 + ni * 8 + tig * 2 + 0], cs[ni][0]);
        atomicAdd(&red[warp_n * 32 + ni * 8 + tig * 2 + 1], cs[ni][1]);
    }
    __syncthreads();
    if (tid < 128) red[tid] = rsqrtf(red[tid] + 1e-6f);
    __syncthreads();

    const int col4 = (tid & 31) * 4;
    const int row0 = tid >> 5;                  // 0..7
    float4 iv;
    iv.x = red[col4]; iv.y = red[col4 + 1];
    iv.z = red[col4 + 2]; iv.w = red[col4 + 3];
    float* base = outb + k0 + col4;
    #pragma unroll 1
    for (int it = 0; it < HW / 8; it++) {       // 288 iterations
        float4* p = (float4*)(base + (size_t)(row0 + it * 8) * HW);
        float4 v = *p;
        v.x *= iv.x; v.y *= iv.y; v.z *= iv.z; v.w *= iv.w;
        *p = v;
    }
}

// ---------------------------------------------------------------------------
extern "C" void kernel_launch(void* const* d_in, const int* in_sizes, int n_in,
                              void* d_out, int out_size) {
    const float* A  = (const float*)d_in[0];   // feature_A [16,512,48,48]
    const float* Bm = (const float*)d_in[1];   // feature_B [16,512,48,48]
    float* out = (float*)d_out;                // [16,2304,48,48]

    uint32_t* At;
    uint4* Apk;
    uint2* Bpk;
    cudaGetSymbolAddress((void**)&At,  g_At);
    cudaGetSymbolAddress((void**)&Apk, g_Apk);
    cudaGetSymbolAddress((void**)&Bpk, g_Bpk);

    dim3 tgrid(HW / 32, CDIM / 32, BATCH);     // 72 x 16 x 16
    dim3 tblock(32, 8);
    pack_transpose_kernel<<<tgrid, tblock>>>(A, At);
    packA2_kernel<<<18432, 256>>>(At, Apk);    // 16*144*64*32 threads
    packB_kernel<<<36864, 256>>>(Bm, Bpk);     // 16*288*64*32 threads

    const int dynsmem = 65536;
    cudaFuncSetAttribute(corr_mma_kernel,
                         cudaFuncAttributeMaxDynamicSharedMemorySize, dynsmem);
    dim3 grid(NLT, BATCH);                     // 18 x 16 = 288 CTAs
    corr_mma_kernel<<<grid, 256, dynsmem>>>(Apk, Bpk, out);
}